// round 1
// baseline (speedup 1.0000x reference)
#include <cuda_runtime.h>
#include <cstdint>

#define NN 100000
#define EE 1600000
#define IN_DIM 256
#define HID 128
#define NCLS 40

// ---------------- scratch (static device globals; no runtime alloc) --------
__device__ int   g_deg[NN];
__device__ int   g_offs[NN + 1];
__device__ int   g_cursor[NN];
__device__ float g_dinv[NN];
__device__ int   g_csr[EE + NN];
__device__ float g_h[(size_t)NN * HID];   // GEMM output (messages)
__device__ float g_a[(size_t)NN * HID];   // aggregated output / next input

// ---------------- degree init (self-loop counts as 1) ----------------------
__global__ void init_deg_kernel() {
    int i = blockIdx.x * blockDim.x + threadIdx.x;
    if (i < NN) g_deg[i] = 1;
}

// ---------------- in-degree histogram over edges ----------------------------
__global__ void hist_kernel(const int* __restrict__ dst) {
    int i = blockIdx.x * blockDim.x + threadIdx.x;
    int stride = gridDim.x * blockDim.x;
    for (; i < EE; i += stride) {
        atomicAdd(&g_deg[dst[i]], 1);
    }
}

// ---------------- single-block exclusive scan + dinv + cursor ---------------
__global__ void scan_kernel() {
    __shared__ int sh[1024];
    __shared__ int carry_sh;
    int tid = threadIdx.x;
    if (tid == 0) carry_sh = 0;
    __syncthreads();
    for (int base = 0; base < NN; base += 1024) {
        int i = base + tid;
        int v = (i < NN) ? g_deg[i] : 0;
        sh[tid] = v;
        __syncthreads();
        // Hillis-Steele inclusive scan
        #pragma unroll
        for (int d = 1; d < 1024; d <<= 1) {
            int t = 0;
            if (tid >= d) t = sh[tid - d];
            __syncthreads();
            sh[tid] += t;
            __syncthreads();
        }
        int incl = sh[tid];
        int excl = incl - v;
        int carry = carry_sh;
        if (i < NN) {
            g_offs[i]   = carry + excl;
            g_cursor[i] = carry + excl;
            g_dinv[i]   = rsqrtf((float)v);
        }
        __syncthreads();
        if (tid == 1023) carry_sh = carry + sh[1023];
        __syncthreads();
    }
    if (tid == 0) g_offs[NN] = carry_sh;
}

// ---------------- CSR fill (edges + self-loops) -----------------------------
__global__ void fill_kernel(const int* __restrict__ src, const int* __restrict__ dst) {
    int i = blockIdx.x * blockDim.x + threadIdx.x;
    int stride = gridDim.x * blockDim.x;
    const int total = EE + NN;
    for (; i < total; i += stride) {
        int s, d;
        if (i < EE) { s = src[i]; d = dst[i]; }
        else        { s = i - EE; d = s; }
        int pos = atomicAdd(&g_cursor[d], 1);
        g_csr[pos] = s;
    }
}

// ---------------- GEMM: C[n,128] = A[n,K] @ W[K,128] ------------------------
// 256 threads per block, 64 rows x 128 cols per block, BK=32.
template <int K>
__global__ void gemm128_kernel(const float* __restrict__ A,
                               const float* __restrict__ W,
                               float* __restrict__ C, int n) {
    constexpr int BK = 32;
    __shared__ float As[64][BK];
    __shared__ float Bs[BK][128];
    const int block_row = blockIdx.x * 64;
    const int tid = threadIdx.x;
    const int tx = tid & 31;    // col group (x4)
    const int ty = tid >> 5;    // row group (x8)

    float acc[8][4];
    #pragma unroll
    for (int i = 0; i < 8; i++)
        #pragma unroll
        for (int j = 0; j < 4; j++) acc[i][j] = 0.f;

    for (int k0 = 0; k0 < K; k0 += BK) {
        // load A tile: 64 x 32 floats = 512 float4, 2 per thread
        #pragma unroll
        for (int r = 0; r < 2; r++) {
            int idx  = tid + r * 256;       // float4 index
            int row  = idx >> 3;            // 8 float4 per row
            int col4 = idx & 7;
            int grow = block_row + row;
            float4 v = make_float4(0.f, 0.f, 0.f, 0.f);
            if (grow < n)
                v = *(const float4*)&A[(size_t)grow * K + k0 + col4 * 4];
            *(float4*)&As[row][col4 * 4] = v;
        }
        // load W tile: 32 x 128 floats = 1024 float4, 4 per thread
        #pragma unroll
        for (int r = 0; r < 4; r++) {
            int idx  = tid + r * 256;
            int row  = idx >> 5;            // 32 float4 per row
            int col4 = idx & 31;
            *(float4*)&Bs[row][col4 * 4] =
                *(const float4*)&W[(size_t)(k0 + row) * 128 + col4 * 4];
        }
        __syncthreads();

        #pragma unroll
        for (int kk = 0; kk < BK; kk++) {
            float4 b = *(const float4*)&Bs[kk][tx * 4];
            #pragma unroll
            for (int i = 0; i < 8; i++) {
                float a = As[ty * 8 + i][kk];
                acc[i][0] += a * b.x;
                acc[i][1] += a * b.y;
                acc[i][2] += a * b.z;
                acc[i][3] += a * b.w;
            }
        }
        __syncthreads();
    }

    #pragma unroll
    for (int i = 0; i < 8; i++) {
        int grow = block_row + ty * 8 + i;
        if (grow < n)
            *(float4*)&C[(size_t)grow * 128 + tx * 4] =
                make_float4(acc[i][0], acc[i][1], acc[i][2], acc[i][3]);
    }
}

// ---------------- GEMM: C[n,40] = A[n,128] @ W[128,40] ----------------------
// one row per thread, W fully in shared.
__global__ void gemm40_kernel(const float* __restrict__ A,
                              const float* __restrict__ W,
                              float* __restrict__ C, int n) {
    __shared__ float Ws[128][NCLS];
    for (int i = threadIdx.x; i < 128 * NCLS; i += blockDim.x)
        Ws[i / NCLS][i % NCLS] = W[i];
    __syncthreads();

    int row = blockIdx.x * blockDim.x + threadIdx.x;
    if (row >= n) return;

    float acc[NCLS];
    #pragma unroll
    for (int c = 0; c < NCLS; c++) acc[c] = 0.f;

    const float4* a4 = (const float4*)(A + (size_t)row * 128);
    for (int k4 = 0; k4 < 32; k4++) {
        float4 a = __ldg(&a4[k4]);
        int k = k4 * 4;
        #pragma unroll
        for (int c = 0; c < NCLS; c++) {
            acc[c] += a.x * Ws[k][c];
            acc[c] += a.y * Ws[k + 1][c];
            acc[c] += a.z * Ws[k + 2][c];
            acc[c] += a.w * Ws[k + 3][c];
        }
    }
    float* out = C + (size_t)row * NCLS;
    #pragma unroll
    for (int c = 0; c < NCLS; c++) out[c] = acc[c];
}

// ---------------- pull-based aggregation ------------------------------------
// One block per destination node. thread tid handles output column tid.
// out[i,c] = dinv[i] * sum_{s in N(i)} dinv[s] * h[s,c]  + bias[c]  (+ReLU)
template <int OUT, bool RELU>
__global__ void agg_kernel(const float* __restrict__ h,
                           const float* __restrict__ bias,
                           float* __restrict__ out) {
    const int node = blockIdx.x;
    const int tid = threadIdx.x;
    const int start = g_offs[node];
    const int end   = g_offs[node + 1];

    float acc = 0.f;
    for (int k = start; k < end; k++) {
        int s   = __ldg(&g_csr[k]);
        float w = __ldg(&g_dinv[s]);
        if (tid < OUT)
            acc += w * __ldg(&h[(size_t)s * OUT + tid]);
    }
    if (tid < OUT) {
        float v = acc * g_dinv[node] + bias[tid];
        if (RELU) v = fmaxf(v, 0.f);
        out[(size_t)node * OUT + tid] = v;
    }
}

// ---------------- launch -----------------------------------------------------
extern "C" void kernel_launch(void* const* d_in, const int* in_sizes, int n_in,
                              void* d_out, int out_size) {
    const float* x   = (const float*)d_in[0];
    const int*   ei  = (const int*)d_in[1];   // [2, E]: row0=src, row1=dst
    const float* W1  = (const float*)d_in[2];
    const float* b1  = (const float*)d_in[3];
    const float* W2  = (const float*)d_in[4];
    const float* b2  = (const float*)d_in[5];
    const float* W3  = (const float*)d_in[6];
    const float* b3  = (const float*)d_in[7];
    float* out = (float*)d_out;

    const int* src = ei;
    const int* dst = ei + EE;

    // ---- graph preprocessing: degree -> scan -> CSR fill ----
    init_deg_kernel<<<(NN + 255) / 256, 256>>>();
    hist_kernel<<<2048, 256>>>(dst);
    scan_kernel<<<1, 1024>>>();
    fill_kernel<<<2048, 256>>>(src, dst);

    // ---- layer 1: h = x @ W1 ; a = agg(h) + b1 ; relu ----
    gemm128_kernel<IN_DIM><<<(NN + 63) / 64, 256>>>(x, W1, g_h, NN);
    agg_kernel<HID, true><<<NN, HID>>>(g_h, b1, g_a);

    // ---- layer 2 ----
    gemm128_kernel<HID><<<(NN + 63) / 64, 256>>>(g_a, W2, g_h, NN);
    agg_kernel<HID, true><<<NN, HID>>>(g_h, b2, g_a);

    // ---- layer 3 ----
    gemm40_kernel<<<(NN + 255) / 256, 256>>>(g_a, W3, g_h, NN);
    agg_kernel<NCLS, false><<<NN, 64>>>(g_h, b3, out);
}

// round 2
// speedup vs baseline: 1.0874x; 1.0874x over previous
#include <cuda_runtime.h>
#include <cstdint>

#define NN 100000
#define EE 1600000
#define IN_DIM 256
#define HID 128
#define NCLS 40

// ---------------- scratch (static device globals; no runtime alloc) --------
__device__ int   g_deg[NN];
__device__ int   g_offs[NN + 1];
__device__ int   g_cursor[NN];
__device__ float g_dinv[NN];
__device__ int   g_csr[EE + NN];
__device__ float g_h[(size_t)NN * HID];   // GEMM output (dinv-prescaled messages)
__device__ float g_a[(size_t)NN * HID];   // aggregated output / next input

// ---------------- degree init (self-loop counts as 1) ----------------------
__global__ void init_deg_kernel() {
    int i = blockIdx.x * blockDim.x + threadIdx.x;
    if (i < NN) g_deg[i] = 1;
}

// ---------------- in-degree histogram over edges ----------------------------
__global__ void hist_kernel(const int* __restrict__ dst) {
    int i = blockIdx.x * blockDim.x + threadIdx.x;
    int stride = gridDim.x * blockDim.x;
    for (; i < EE; i += stride) {
        atomicAdd(&g_deg[dst[i]], 1);
    }
}

// ---------------- single-block exclusive scan (warp-shuffle) ----------------
__global__ void scan_kernel() {
    __shared__ int warp_sums[32];
    __shared__ int carry_sh;
    const int tid  = threadIdx.x;
    const int lane = tid & 31;
    const int wid  = tid >> 5;
    if (tid == 0) carry_sh = 0;
    __syncthreads();
    for (int base = 0; base < NN; base += 1024) {
        int i = base + tid;
        int v = (i < NN) ? g_deg[i] : 0;
        // warp inclusive scan
        int x = v;
        #pragma unroll
        for (int d = 1; d < 32; d <<= 1) {
            int t = __shfl_up_sync(0xFFFFFFFFu, x, d);
            if (lane >= d) x += t;
        }
        if (lane == 31) warp_sums[wid] = x;
        __syncthreads();
        if (wid == 0) {
            int s = warp_sums[lane];
            #pragma unroll
            for (int d = 1; d < 32; d <<= 1) {
                int t = __shfl_up_sync(0xFFFFFFFFu, s, d);
                if (lane >= d) s += t;
            }
            warp_sums[lane] = s;
        }
        __syncthreads();
        int warp_off = (wid == 0) ? 0 : warp_sums[wid - 1];
        int incl = x + warp_off;
        int excl = incl - v;
        int carry = carry_sh;
        if (i < NN) {
            g_offs[i]   = carry + excl;
            g_cursor[i] = carry + excl;
            g_dinv[i]   = rsqrtf((float)v);
        }
        __syncthreads();
        if (tid == 1023) carry_sh = carry + incl;  // incl of last thread = tile total
        __syncthreads();
    }
    if (tid == 0) g_offs[NN] = carry_sh;
}

// ---------------- CSR fill (edges + self-loops) -----------------------------
__global__ void fill_kernel(const int* __restrict__ src, const int* __restrict__ dst) {
    int i = blockIdx.x * blockDim.x + threadIdx.x;
    int stride = gridDim.x * blockDim.x;
    const int total = EE + NN;
    for (; i < total; i += stride) {
        int s, d;
        if (i < EE) { s = src[i]; d = dst[i]; }
        else        { s = i - EE; d = s; }
        int pos = atomicAdd(&g_cursor[d], 1);
        g_csr[pos] = s;
    }
}

// ---------------- GEMM: C[n,128] = dinv[row] * (A[n,K] @ W[K,128]) ----------
// 256 threads per block, 64 rows x 128 cols per block, BK=32.
template <int K>
__global__ void __launch_bounds__(256) gemm128_kernel(
        const float* __restrict__ A, const float* __restrict__ W,
        float* __restrict__ C, int n) {
    constexpr int BK = 32;
    __shared__ float As[64][BK];
    __shared__ float Bs[BK][128];
    const int block_row = blockIdx.x * 64;
    const int tid = threadIdx.x;
    const int tx = tid & 31;    // col group (x4)
    const int ty = tid >> 5;    // row group (x8)

    float acc[8][4];
    #pragma unroll
    for (int i = 0; i < 8; i++)
        #pragma unroll
        for (int j = 0; j < 4; j++) acc[i][j] = 0.f;

    for (int k0 = 0; k0 < K; k0 += BK) {
        #pragma unroll
        for (int r = 0; r < 2; r++) {
            int idx  = tid + r * 256;       // float4 index
            int row  = idx >> 3;            // 8 float4 per row
            int col4 = idx & 7;
            int grow = block_row + row;
            float4 v = make_float4(0.f, 0.f, 0.f, 0.f);
            if (grow < n)
                v = *(const float4*)&A[(size_t)grow * K + k0 + col4 * 4];
            *(float4*)&As[row][col4 * 4] = v;
        }
        #pragma unroll
        for (int r = 0; r < 4; r++) {
            int idx  = tid + r * 256;
            int row  = idx >> 5;            // 32 float4 per row
            int col4 = idx & 31;
            *(float4*)&Bs[row][col4 * 4] =
                *(const float4*)&W[(size_t)(k0 + row) * 128 + col4 * 4];
        }
        __syncthreads();

        #pragma unroll
        for (int kk = 0; kk < BK; kk++) {
            float4 b = *(const float4*)&Bs[kk][tx * 4];
            #pragma unroll
            for (int i = 0; i < 8; i++) {
                float a = As[ty * 8 + i][kk];
                acc[i][0] += a * b.x;
                acc[i][1] += a * b.y;
                acc[i][2] += a * b.z;
                acc[i][3] += a * b.w;
            }
        }
        __syncthreads();
    }

    #pragma unroll
    for (int i = 0; i < 8; i++) {
        int grow = block_row + ty * 8 + i;
        if (grow < n) {
            float d = g_dinv[grow];
            *(float4*)&C[(size_t)grow * 128 + tx * 4] =
                make_float4(acc[i][0] * d, acc[i][1] * d, acc[i][2] * d, acc[i][3] * d);
        }
    }
}

// ---------------- GEMM: C[n,40] = dinv[row] * (A[n,128] @ W[128,40]) --------
__global__ void __launch_bounds__(256) gemm40_kernel(
        const float* __restrict__ A, const float* __restrict__ W,
        float* __restrict__ C, int n) {
    __shared__ float Ws[128][NCLS];
    for (int i = threadIdx.x; i < 128 * NCLS; i += blockDim.x)
        Ws[i / NCLS][i % NCLS] = W[i];
    __syncthreads();

    int row = blockIdx.x * blockDim.x + threadIdx.x;
    if (row >= n) return;

    float acc[NCLS];
    #pragma unroll
    for (int c = 0; c < NCLS; c++) acc[c] = 0.f;

    const float4* a4 = (const float4*)(A + (size_t)row * 128);
    for (int k4 = 0; k4 < 32; k4++) {
        float4 a = __ldg(&a4[k4]);
        int k = k4 * 4;
        #pragma unroll
        for (int c = 0; c < NCLS; c++) {
            acc[c] += a.x * Ws[k][c];
            acc[c] += a.y * Ws[k + 1][c];
            acc[c] += a.z * Ws[k + 2][c];
            acc[c] += a.w * Ws[k + 3][c];
        }
    }
    float d = g_dinv[row];
    float* out = C + (size_t)row * NCLS;
    #pragma unroll
    for (int c = 0; c < NCLS; c++) out[c] = acc[c] * d;
}

// ---------------- aggregation, 128 cols: warp-per-node, 4-deep pipeline -----
// h rows are prescaled by dinv[src]; out[i] = dinv[i]*sum + bias (+ReLU)
template <bool RELU>
__global__ void __launch_bounds__(256) agg128_kernel(
        const float* __restrict__ h, const float* __restrict__ bias,
        float* __restrict__ out) {
    const int lane = threadIdx.x & 31;
    const int gw   = (blockIdx.x * 256 + threadIdx.x) >> 5;
    const int nw   = (gridDim.x * 256) >> 5;
    const float4 bv = ((const float4*)bias)[lane];
    const float4* __restrict__ h4 = (const float4*)h;

    for (int node = gw; node < NN; node += nw) {
        const int start = g_offs[node];
        const int end   = g_offs[node + 1];
        float4 acc = make_float4(0.f, 0.f, 0.f, 0.f);
        int k = start;
        for (; k + 4 <= end; k += 4) {
            const int s0 = __ldg(&g_csr[k + 0]);
            const int s1 = __ldg(&g_csr[k + 1]);
            const int s2 = __ldg(&g_csr[k + 2]);
            const int s3 = __ldg(&g_csr[k + 3]);
            float4 v0 = __ldg(h4 + (size_t)s0 * 32 + lane);
            float4 v1 = __ldg(h4 + (size_t)s1 * 32 + lane);
            float4 v2 = __ldg(h4 + (size_t)s2 * 32 + lane);
            float4 v3 = __ldg(h4 + (size_t)s3 * 32 + lane);
            acc.x += (v0.x + v1.x) + (v2.x + v3.x);
            acc.y += (v0.y + v1.y) + (v2.y + v3.y);
            acc.z += (v0.z + v1.z) + (v2.z + v3.z);
            acc.w += (v0.w + v1.w) + (v2.w + v3.w);
        }
        for (; k < end; k++) {
            const int s = __ldg(&g_csr[k]);
            float4 v = __ldg(h4 + (size_t)s * 32 + lane);
            acc.x += v.x; acc.y += v.y; acc.z += v.z; acc.w += v.w;
        }
        const float d = g_dinv[node];
        float4 r;
        r.x = fmaf(acc.x, d, bv.x);
        r.y = fmaf(acc.y, d, bv.y);
        r.z = fmaf(acc.z, d, bv.z);
        r.w = fmaf(acc.w, d, bv.w);
        if (RELU) {
            r.x = fmaxf(r.x, 0.f); r.y = fmaxf(r.y, 0.f);
            r.z = fmaxf(r.z, 0.f); r.w = fmaxf(r.w, 0.f);
        }
        ((float4*)out)[(size_t)node * 32 + lane] = r;
    }
}

// ---------------- aggregation, 40 cols: warp-per-node, float2 lanes ---------
__global__ void __launch_bounds__(256) agg40_kernel(
        const float* __restrict__ h, const float* __restrict__ bias,
        float* __restrict__ out) {
    const int lane = threadIdx.x & 31;
    const int gw   = (blockIdx.x * 256 + threadIdx.x) >> 5;
    const int nw   = (gridDim.x * 256) >> 5;
    const bool act = lane < 20;
    float2 bv = make_float2(0.f, 0.f);
    if (act) bv = ((const float2*)bias)[lane];

    for (int node = gw; node < NN; node += nw) {
        const int start = g_offs[node];
        const int end   = g_offs[node + 1];
        float2 acc = make_float2(0.f, 0.f);
        int k = start;
        for (; k + 4 <= end; k += 4) {
            const int s0 = __ldg(&g_csr[k + 0]);
            const int s1 = __ldg(&g_csr[k + 1]);
            const int s2 = __ldg(&g_csr[k + 2]);
            const int s3 = __ldg(&g_csr[k + 3]);
            if (act) {
                float2 v0 = __ldg((const float2*)(h + (size_t)s0 * NCLS) + lane);
                float2 v1 = __ldg((const float2*)(h + (size_t)s1 * NCLS) + lane);
                float2 v2 = __ldg((const float2*)(h + (size_t)s2 * NCLS) + lane);
                float2 v3 = __ldg((const float2*)(h + (size_t)s3 * NCLS) + lane);
                acc.x += (v0.x + v1.x) + (v2.x + v3.x);
                acc.y += (v0.y + v1.y) + (v2.y + v3.y);
            }
        }
        for (; k < end; k++) {
            const int s = __ldg(&g_csr[k]);
            if (act) {
                float2 v = __ldg((const float2*)(h + (size_t)s * NCLS) + lane);
                acc.x += v.x; acc.y += v.y;
            }
        }
        if (act) {
            const float d = g_dinv[node];
            float2 r;
            r.x = fmaf(acc.x, d, bv.x);
            r.y = fmaf(acc.y, d, bv.y);
            ((float2*)(out + (size_t)node * NCLS))[lane] = r;
        }
    }
}

// ---------------- launch -----------------------------------------------------
extern "C" void kernel_launch(void* const* d_in, const int* in_sizes, int n_in,
                              void* d_out, int out_size) {
    const float* x   = (const float*)d_in[0];
    const int*   ei  = (const int*)d_in[1];   // [2, E]: row0=src, row1=dst
    const float* W1  = (const float*)d_in[2];
    const float* b1  = (const float*)d_in[3];
    const float* W2  = (const float*)d_in[4];
    const float* b2  = (const float*)d_in[5];
    const float* W3  = (const float*)d_in[6];
    const float* b3  = (const float*)d_in[7];
    float* out = (float*)d_out;

    const int* src = ei;
    const int* dst = ei + EE;

    // ---- graph preprocessing: degree -> scan -> CSR fill ----
    init_deg_kernel<<<(NN + 255) / 256, 256>>>();
    hist_kernel<<<2048, 256>>>(dst);
    scan_kernel<<<1, 1024>>>();
    fill_kernel<<<2048, 256>>>(src, dst);

    const int AGG_BLOCKS = 148 * 16;

    // ---- layer 1 ----
    gemm128_kernel<IN_DIM><<<(NN + 63) / 64, 256>>>(x, W1, g_h, NN);
    agg128_kernel<true><<<AGG_BLOCKS, 256>>>(g_h, b1, g_a);

    // ---- layer 2 ----
    gemm128_kernel<HID><<<(NN + 63) / 64, 256>>>(g_a, W2, g_h, NN);
    agg128_kernel<true><<<AGG_BLOCKS, 256>>>(g_h, b2, g_a);

    // ---- layer 3 ----
    gemm40_kernel<<<(NN + 255) / 256, 256>>>(g_a, W3, g_h, NN);
    agg40_kernel<<<AGG_BLOCKS, 256>>>(g_h, b3, out);
}